// round 2
// baseline (speedup 1.0000x reference)
#include <cuda_runtime.h>

static constexpr int NV   = 48;
static constexpr int NP1  = 49;
static constexpr int NB   = 98;
static constexpr int NSEG = 65536;
static constexpr int RPB  = 4;     // rows per block

static constexpr float PW0 = 0.01f;
static constexpr float PW1 = 0.005f;

// hash scratch (device globals — no allocations allowed)
__device__ float g_seg[2 * NSEG];
__device__ int   g_cnt[2 * NSEG];

struct RowS {
    float sd[NP1];
    float w[NV];
    float wn[NV];
    float bounds[NB];
    float rs[NB];
    float wb[NB];
    float cdf[NB];
    float res[288];   // covers XP up to 288 (need 257)
};

__device__ __forceinline__ float warpsum(float v) {
    #pragma unroll
    for (int o = 16; o; o >>= 1) v += __shfl_xor_sync(0xffffffffu, v, o);
    return v;
}

__device__ __forceinline__ float warp_excl_from_total(float tot, int lane) {
    float inc = tot;
    #pragma unroll
    for (int o = 1; o < 32; o <<= 1) {
        float y = __shfl_up_sync(0xffffffffu, inc, o);
        if (lane >= o) inc += y;
    }
    return inc - tot;
}

// ---- batched interp: all P points of a lane advance their searches in lockstep ----
template <int P>
__device__ __forceinline__ float interp_level(RowS& S, const float* __restrict__ psd,
                                              const float* __restrict__ pwt,
                                              int row, int XP, int lane, float scale)
{
    float x[P]; int lo[P], hi[P]; bool act[P];
    #pragma unroll
    for (int j = 0; j < P; ++j) {
        int t = lane + 32 * j;
        act[j] = t < XP;
        x[j] = act[j] ? psd[row * XP + t] : 0.f;
        lo[j] = 0; hi[j] = NB;
    }
    // search1: k = upper_bound(bounds, x) - 1   (7 steps for NB=98)
    #pragma unroll
    for (int s = 0; s < 7; ++s) {
        #pragma unroll
        for (int j = 0; j < P; ++j) {
            if (act[j] && lo[j] < hi[j]) {
                int mid = (lo[j] + hi[j]) >> 1;
                if (S.bounds[mid] <= x[j]) lo[j] = mid + 1; else hi[j] = mid;
            }
        }
    }
    int karr[P], kk[P]; float fcdf0[P];
    #pragma unroll
    for (int j = 0; j < P; ++j) {
        int k = lo[j] - 1;
        karr[j] = k;
        kk[j] = k < 0 ? 0 : k;
        fcdf0[j] = act[j] ? S.cdf[kk[j]] : 0.f;
        lo[j] = 0; hi[j] = NB;
    }
    // search2: i0 = lower_bound(cdf, fcdf0)  (first-index argmax under ties)
    #pragma unroll
    for (int s = 0; s < 7; ++s) {
        #pragma unroll
        for (int j = 0; j < P; ++j) {
            if (act[j] && lo[j] < hi[j]) {
                int mid = (lo[j] + hi[j]) >> 1;
                if (S.cdf[mid] < fcdf0[j]) lo[j] = mid + 1; else hi[j] = mid;
            }
        }
    }
    float cdfN = S.cdf[NB - 1];
    #pragma unroll
    for (int j = 0; j < P; ++j) {
        if (!act[j]) continue;
        int k = karr[j];
        float xp0 = S.bounds[kk[j]];
        int i1; float xp1;
        if (k < 0)            { i1 = 0; xp1 = S.bounds[0]; }
        else if (k >= NB - 1) { i1 = 0; xp1 = S.bounds[NB - 1]; }
        else {
            float ck1 = S.cdf[k + 1];
            i1 = (ck1 == cdfN) ? 0 : (k + 1);
            xp1 = S.bounds[k + 1];
        }
        float fp0 = S.wb[lo[j]];
        float fp1 = S.wb[i1];
        float num = x[j] - xp0, den = xp1 - xp0;
        float off = (den > 0.f) ? fminf(fmaxf(num / den, 0.f), 1.f)
                                : (num > 0.f ? 1.f : 0.f);
        S.res[lane + 32 * j] = fcdf0[j] + num * (fp0 + fp1 * off + fp0 * (1.f - off)) * 0.5f;
    }
    __syncwarp();

    float lsum = 0.f;
    for (int t = lane; t < XP - 1; t += 32) {
        float ws  = S.res[t + 1] - S.res[t];
        float pwv = pwt[row * (XP - 1) + t];
        float d = ws - pwv;
        if (d > 0.f) lsum += d * d / (pwv + 1e-5f);
    }
    __syncwarp();
    return lsum * scale;
}

__global__ __launch_bounds__(RPB * 32)
void row_kernel(const float* __restrict__ pd, const float* __restrict__ gt,
                const float* __restrict__ rsd, const float* __restrict__ rw,
                const float* __restrict__ psd0, const float* __restrict__ pwt0,
                const float* __restrict__ psd1, const float* __restrict__ pwt1,
                float* __restrict__ out, int R, int XP0, int XP1)
{
    __shared__ RowS sm[RPB];
    __shared__ float bacc[RPB];

    const int warp = threadIdx.x >> 5;
    const int lane = threadIdx.x & 31;
    const int row  = blockIdx.x * RPB + warp;

    float acc = 0.f;
    float p1 = 0.f, p2 = 0.f;

    if (row < R) {
        RowS& S = sm[warp];

        for (int i = lane; i < NP1; i += 32) S.sd[i] = rsd[row * NP1 + i];
        __syncwarp();
        for (int i = lane; i < NV; i += 32) {
            float wv = rw[row * NV + i];
            S.w[i]  = wv;
            S.wn[i] = wv / (S.sd[i + 1] - S.sd[i] + 1e-8f);
            S.rs[i] = 0.5f * (S.sd[i + 1] + S.sd[i]);   // temp: midpoints for distortion
        }
        __syncwarp();

        if (lane < 3) {
            float d = pd[row * 3 + lane] - gt[row * 3 + lane];
            acc += d * d / (3.f * (float)R);
        }

        // distortion
        for (int n = lane; n < NV; n += 32) {
            float mn = S.rs[n];
            float wv = S.w[n];
            float inner = 0.f;
            #pragma unroll 8
            for (int m = 0; m < NV; ++m)
                inner += S.w[m] * fabsf(mn - S.rs[m]);
            p1 += wv * inner;
            p2 += wv * wv * (S.sd[n + 1] - S.sd[n]);
        }
        __syncwarp();

        #pragma unroll 1
        for (int lev = 0; lev < 2; ++lev) {
            const float pw = lev ? PW1 : PW0;
            const float* psd = lev ? psd1 : psd0;
            const float* pwt = lev ? pwt1 : pwt0;
            const int XP = lev ? XP1 : XP0;
            const float scale = 1.f / ((float)R * (float)(XP - 1));

            // -- batched stable merge (rank-scatter), 4 positions per lane --
            {
                int   mlo[4]; float mval[4]; int mj[4]; bool mok[4], mlow[4];
                #pragma unroll
                for (int q = 0; q < 4; ++q) {
                    int p = lane + 32 * q;
                    mok[q]  = p < NB;
                    mlow[q] = p < NP1;
                    int j   = mlow[q] ? p : p - NP1;
                    mj[q]   = j;
                    mval[q] = mok[q] ? (mlow[q] ? S.sd[j] - pw : S.sd[j] + pw) : 0.f;
                    mlo[q]  = 0;
                }
                int mhi[4] = {NP1, NP1, NP1, NP1};
                #pragma unroll
                for (int s = 0; s < 6; ++s) {
                    #pragma unroll
                    for (int q = 0; q < 4; ++q) {
                        if (mok[q] && mlo[q] < mhi[q]) {
                            int mid = (mlo[q] + mhi[q]) >> 1;
                            float sv = S.sd[mid];
                            bool adv = mlow[q] ? (sv + pw < mval[q]) : (sv - pw <= mval[q]);
                            if (adv) mlo[q] = mid + 1; else mhi[q] = mid;
                        }
                    }
                }
                #pragma unroll
                for (int q = 0; q < 4; ++q) {
                    if (mok[q]) {
                        int j = mj[q];
                        float d0 = (j < NV ? S.wn[j] : 0.f) - (j > 0 ? S.wn[j - 1] : 0.f);
                        float rv = (mlow[q] ? d0 : -d0) / (2.f * pw);
                        int pos = j + mlo[q];
                        S.bounds[pos] = mval[q];
                        S.rs[pos] = rv;
                    }
                }
            }
            __syncwarp();

            // -- three blocked scans over 97 elements --
            const int base = lane * 4;
            float r4[4], ds4[4];
            #pragma unroll
            for (int t = 0; t < 4; ++t) {
                int k = base + t;
                bool v = (k < NB - 1);
                r4[t]  = v ? S.rs[k] : 0.f;
                ds4[t] = v ? (S.bounds[k + 1] - S.bounds[k]) : 0.f;
            }
            float c = 0.f, cum4[4];
            #pragma unroll
            for (int t = 0; t < 4; ++t) { c += r4[t]; cum4[t] = c; }
            float carry1 = warp_excl_from_total(c, lane);
            float c2 = 0.f, rec4[4];
            #pragma unroll
            for (int t = 0; t < 4; ++t) { c2 += ds4[t] * (cum4[t] + carry1); rec4[t] = c2; }
            float carry2 = warp_excl_from_total(c2, lane);
            float c3 = 0.f, cdf4[4], wb4[4];
            float wprev = (base == 0) ? 0.f : fmaxf(carry2, 0.f);
            #pragma unroll
            for (int t = 0; t < 4; ++t) {
                float wbk1 = fmaxf(rec4[t] + carry2, 0.f);
                wb4[t] = wbk1;
                c3 += 0.5f * (wbk1 + wprev) * ds4[t];
                cdf4[t] = c3;
                wprev = wbk1;
            }
            float carry3 = warp_excl_from_total(c3, lane);
            #pragma unroll
            for (int t = 0; t < 4; ++t) {
                int k = base + t;
                if (k < NB - 1) {
                    S.wb[k + 1]  = wb4[t];
                    S.cdf[k + 1] = cdf4[t] + carry3;
                }
            }
            if (lane == 0) { S.wb[0] = 0.f; S.cdf[0] = 0.f; }
            __syncwarp();

            if (lev == 0) acc += interp_level<9>(S, psd, pwt, row, XP, lane, scale);
            else          acc += interp_level<4>(S, psd, pwt, row, XP, lane, scale);
        }
    }

    float wa = warpsum(acc);
    float P1 = warpsum(p1);
    float P2 = warpsum(p2);
    if (lane == 0)
        bacc[warp] = (row < R) ? (wa + (fabsf(P1) + fabsf(P2 * (1.f / 3.f))) * (0.01f / (float)R))
                               : 0.f;
    __syncthreads();
    if (threadIdx.x == 0) {
        float t = 0.f;
        #pragma unroll
        for (int i = 0; i < RPB; ++i) t += bacc[i];
        atomicAdd(out, t);
    }
}

// ---- hash path: zero scratch -> warp-aggregated scatter -> reduce ----
__global__ __launch_bounds__(256)
void zero_kernel(float* out)
{
    int i = blockIdx.x * blockDim.x + threadIdx.x;
    if (i < 2 * NSEG) { g_seg[i] = 0.f; g_cnt[i] = 0; }
    if (i == 0) out[0] = 0.f;
}

__global__ __launch_bounds__(256)
void hash_scatter(const float* __restrict__ emb, const int* __restrict__ idx,
                  int M, int slot)
{
    int i = blockIdx.x * blockDim.x + threadIdx.x;
    int lane = threadIdx.x & 31;
    bool ok = i < M;
    int s = ok ? idx[i] : -1;
    float v = 0.f;
    if (ok) {
        float2 e = ((const float2*)emb)[i];
        v = e.x * e.x + e.y * e.y;
    }
    // idx sorted -> equal-index lanes are contiguous in the warp
    unsigned m = __match_any_sync(0xffffffffu, s);
    int leader = __ffs(m) - 1;
    int hib = 31 - __clz(m);
    #pragma unroll
    for (int o = 16; o; o >>= 1) {
        float y = __shfl_down_sync(0xffffffffu, v, o);
        if (lane + o <= hib) v += y;
    }
    if (ok && lane == leader) {
        atomicAdd(&g_seg[slot * NSEG + s], v);
        atomicAdd(&g_cnt[slot * NSEG + s], __popc(m));
    }
}

__global__ __launch_bounds__(256)
void hash_reduce(float* out)
{
    int i = blockIdx.x * blockDim.x + threadIdx.x;
    float v = 0.f;
    if (i < 2 * NSEG) {
        int c = g_cnt[i];
        v = (c > 0) ? g_seg[i] / (float)c : 0.f;
    }
    v = warpsum(v);
    __shared__ float sh[8];
    int w = threadIdx.x >> 5, l = threadIdx.x & 31;
    if (l == 0) sh[w] = v;
    __syncthreads();
    if (w == 0) {
        float t = (l < 8) ? sh[l] : 0.f;
        t = warpsum(t);
        if (l == 0) atomicAdd(out, t * (0.1f / (2.f * (float)NSEG)));
    }
}

extern "C" void kernel_launch(void* const* d_in, const int* in_sizes, int n_in,
                              void* d_out, int out_size)
{
    const float* pd   = (const float*)d_in[0];
    const float* gt   = (const float*)d_in[1];
    const float* rsd  = (const float*)d_in[2];
    const float* rw   = (const float*)d_in[3];
    const float* psd0 = (const float*)d_in[4];
    const float* pwt0 = (const float*)d_in[5];
    const float* psd1 = (const float*)d_in[6];
    const float* pwt1 = (const float*)d_in[7];
    const float* emb0 = (const float*)d_in[8];
    const float* emb1 = (const float*)d_in[9];
    const int*   idx0 = (const int*)d_in[10];
    const int*   idx1 = (const int*)d_in[11];
    float* out = (float*)d_out;

    const int R   = in_sizes[0] / 3;
    const int XP0 = in_sizes[4] / R;
    const int XP1 = in_sizes[6] / R;
    const int M   = in_sizes[8] / 2;

    zero_kernel<<<(2 * NSEG + 255) / 256, 256>>>(out);

    hash_scatter<<<(M + 255) / 256, 256>>>(emb0, idx0, M, 0);
    hash_scatter<<<(M + 255) / 256, 256>>>(emb1, idx1, M, 1);
    hash_reduce<<<(2 * NSEG + 255) / 256, 256>>>(out);

    row_kernel<<<(R + RPB - 1) / RPB, RPB * 32>>>(pd, gt, rsd, rw,
                                                  psd0, pwt0, psd1, pwt1,
                                                  out, R, XP0, XP1);
}

// round 3
// speedup vs baseline: 1.4159x; 1.4159x over previous
#include <cuda_runtime.h>

static constexpr int NV   = 48;
static constexpr int NP1  = 49;
static constexpr int NB   = 98;
static constexpr int NSEG = 65536;
static constexpr int RPB  = 8;     // rows per block (8 warps)

static constexpr float PW0 = 0.01f;
static constexpr float PW1 = 0.005f;

// hash scratch (device globals — allocations are forbidden)
__device__ float g_seg[2 * NSEG];
__device__ int   g_cnt[2 * NSEG];

struct RowS {
    float sd[NP1];
    float w[NV];
    float wn[NV];
    float bounds[NB];
    float rs[NB];      // also temp for midpoints
    float wb[NB];
    float cdf[NB];
    int   ieq[NB];     // first index of equal-cdf run
    float res[260];
};

__device__ __forceinline__ float warpsum(float v) {
    #pragma unroll
    for (int o = 16; o; o >>= 1) v += __shfl_xor_sync(0xffffffffu, v, o);
    return v;
}

__device__ __forceinline__ float warp_excl_from_total(float tot, int lane) {
    float inc = tot;
    #pragma unroll
    for (int o = 1; o < 32; o <<= 1) {
        float y = __shfl_up_sync(0xffffffffu, inc, o);
        if (lane >= o) inc += y;
    }
    return inc - tot;
}

// interp over XP points in strips of 128 (4 per lane, stride-32 layout)
__device__ __forceinline__ float interp_level(RowS& S, const float* __restrict__ psd,
                                              const float* __restrict__ pwt,
                                              int row, int XP, int nstrip,
                                              int lane, float scale)
{
    const float cdfN = S.cdf[NB - 1];
    int kprev = 0;
    #pragma unroll 1
    for (int s = 0; s < nstrip; ++s) {
        float x[4]; int lo[4], hi[4]; bool act[4];
        #pragma unroll
        for (int j = 0; j < 4; ++j) {
            int t = s * 128 + j * 32 + lane;
            act[j] = t < XP;
            x[j] = act[j] ? psd[row * XP + t] : 0.f;
            lo[j] = kprev; hi[j] = NB;
        }
        // k = upper_bound(bounds, x) - 1 ; 4 searches advance together (MLP=4)
        #pragma unroll
        for (int st = 0; st < 7; ++st) {
            #pragma unroll
            for (int j = 0; j < 4; ++j) {
                if (act[j] && lo[j] < hi[j]) {
                    int mid = (lo[j] + hi[j]) >> 1;
                    if (S.bounds[mid] <= x[j]) lo[j] = mid + 1; else hi[j] = mid;
                }
            }
        }
        #pragma unroll
        for (int j = 0; j < 4; ++j) {
            if (!act[j]) continue;
            int k  = lo[j] - 1;
            int kk = k < 0 ? 0 : k;
            kprev  = kk;                    // floor for next strip (per-lane monotone)
            float fcdf0 = S.cdf[kk];
            int   i0    = S.ieq[kk];        // lower_bound(cdf, cdf[kk]) via table
            float xp0   = S.bounds[kk];
            int i1; float xp1;
            if (k < 0)            { i1 = 0; xp1 = S.bounds[0]; }
            else if (k >= NB - 1) { i1 = 0; xp1 = S.bounds[NB - 1]; }
            else {
                float ck1 = S.cdf[k + 1];
                i1 = (ck1 == cdfN) ? 0 : (k + 1);
                xp1 = S.bounds[k + 1];
            }
            float fp0 = S.wb[i0], fp1 = S.wb[i1];
            float num = x[j] - xp0, den = xp1 - xp0;
            float off = (den > 0.f) ? fminf(fmaxf(num / den, 0.f), 1.f)
                                    : (num > 0.f ? 1.f : 0.f);
            S.res[s * 128 + j * 32 + lane] =
                fcdf0 + num * (fp0 + fp1 * off + fp0 * (1.f - off)) * 0.5f;
        }
    }
    __syncwarp();

    float lsum = 0.f;
    for (int t = lane; t < XP - 1; t += 32) {
        float ws  = S.res[t + 1] - S.res[t];
        float pwv = pwt[row * (XP - 1) + t];
        float d = ws - pwv;
        if (d > 0.f) lsum += d * d / (pwv + 1e-5f);
    }
    __syncwarp();
    return lsum * scale;
}

__global__ __launch_bounds__(256)
void mega_kernel(const float* __restrict__ pd, const float* __restrict__ gt,
                 const float* __restrict__ rsd, const float* __restrict__ rw,
                 const float* __restrict__ psd0, const float* __restrict__ pwt0,
                 const float* __restrict__ psd1, const float* __restrict__ pwt1,
                 const float* __restrict__ emb0, const float* __restrict__ emb1,
                 const int* __restrict__ idx0, const int* __restrict__ idx1,
                 float* __restrict__ out, int R, int XP0, int XP1, int M,
                 int ROWB, int HB)
{
    if (blockIdx.x >= (unsigned)ROWB) {
        // ---------------- hash scatter role ----------------
        int h     = blockIdx.x - ROWB;
        int level = h / HB;
        int bh    = h % HB;
        const float* emb = level ? emb1 : emb0;
        const int*   idx = level ? idx1 : idx0;
        const int lane = threadIdx.x & 31;
        const int base = bh * 1024;
        #pragma unroll
        for (int it = 0; it < 4; ++it) {
            int i = base + it * 256 + threadIdx.x;
            bool ok = i < M;
            int s = ok ? idx[i] : -1;
            float v = 0.f;
            if (ok) {
                float2 e = ((const float2*)emb)[i];
                v = e.x * e.x + e.y * e.y;
            }
            unsigned m = __match_any_sync(0xffffffffu, s);
            int leader = __ffs(m) - 1;
            int hib = 31 - __clz(m);
            #pragma unroll
            for (int o = 16; o; o >>= 1) {
                float y = __shfl_down_sync(0xffffffffu, v, o);
                if (lane + o <= hib) v += y;
            }
            if (ok && lane == leader) {
                atomicAdd(&g_seg[level * NSEG + s], v);
                atomicAdd(&g_cnt[level * NSEG + s], __popc(m));
            }
        }
        return;
    }

    // ---------------- row role ----------------
    __shared__ RowS sm[RPB];
    __shared__ float bacc[RPB];

    const int warp = threadIdx.x >> 5;
    const int lane = threadIdx.x & 31;
    const int row  = blockIdx.x * RPB + warp;

    float acc = 0.f;
    float p1 = 0.f, p2 = 0.f;

    if (row < R) {
        RowS& S = sm[warp];

        for (int i = lane; i < NP1; i += 32) S.sd[i] = rsd[row * NP1 + i];
        __syncwarp();
        for (int i = lane; i < NV; i += 32) {
            float wv = rw[row * NV + i];
            S.w[i]  = wv;
            S.wn[i] = wv / (S.sd[i + 1] - S.sd[i] + 1e-8f);
            S.rs[i] = 0.5f * (S.sd[i + 1] + S.sd[i]);   // midpoints (temp)
        }
        __syncwarp();

        if (lane < 3) {
            float d = pd[row * 3 + lane] - gt[row * 3 + lane];
            acc += d * d / (3.f * (float)R);
        }

        for (int n = lane; n < NV; n += 32) {
            float mn = S.rs[n];
            float wv = S.w[n];
            float inner = 0.f;
            #pragma unroll 8
            for (int m = 0; m < NV; ++m)
                inner += S.w[m] * fabsf(mn - S.rs[m]);
            p1 += wv * inner;
            p2 += wv * wv * (S.sd[n + 1] - S.sd[n]);
        }
        __syncwarp();

        #pragma unroll 1
        for (int lev = 0; lev < 2; ++lev) {
            const float pw = lev ? PW1 : PW0;
            const float* psd = lev ? psd1 : psd0;
            const float* pwt = lev ? pwt1 : pwt0;
            const int XP = lev ? XP1 : XP0;
            const float scale = 1.f / ((float)R * (float)(XP - 1));

            // -- batched stable merge (rank-scatter), 4 per lane --
            {
                int   mlo[4]; float mval[4]; int mj[4]; bool mok[4], mlow[4];
                #pragma unroll
                for (int q = 0; q < 4; ++q) {
                    int p = lane + 32 * q;
                    mok[q]  = p < NB;
                    mlow[q] = p < NP1;
                    int j   = mlow[q] ? p : p - NP1;
                    mj[q]   = j;
                    mval[q] = mok[q] ? (mlow[q] ? S.sd[j] - pw : S.sd[j] + pw) : 0.f;
                    mlo[q]  = 0;
                }
                int mhi[4] = {NP1, NP1, NP1, NP1};
                #pragma unroll
                for (int s = 0; s < 6; ++s) {
                    #pragma unroll
                    for (int q = 0; q < 4; ++q) {
                        if (mok[q] && mlo[q] < mhi[q]) {
                            int mid = (mlo[q] + mhi[q]) >> 1;
                            float sv = S.sd[mid];
                            bool adv = mlow[q] ? (sv + pw < mval[q]) : (sv - pw <= mval[q]);
                            if (adv) mlo[q] = mid + 1; else mhi[q] = mid;
                        }
                    }
                }
                #pragma unroll
                for (int q = 0; q < 4; ++q) {
                    if (mok[q]) {
                        int j = mj[q];
                        float d0 = (j < NV ? S.wn[j] : 0.f) - (j > 0 ? S.wn[j - 1] : 0.f);
                        float rv = (mlow[q] ? d0 : -d0) / (2.f * pw);
                        int pos = j + mlo[q];
                        S.bounds[pos] = mval[q];
                        S.rs[pos] = rv;
                    }
                }
            }
            __syncwarp();

            // -- three blocked scans over 97 elements --
            const int base = lane * 4;
            float r4[4], ds4[4];
            #pragma unroll
            for (int t = 0; t < 4; ++t) {
                int k = base + t;
                bool v = (k < NB - 1);
                r4[t]  = v ? S.rs[k] : 0.f;
                ds4[t] = v ? (S.bounds[k + 1] - S.bounds[k]) : 0.f;
            }
            float c = 0.f, cum4[4];
            #pragma unroll
            for (int t = 0; t < 4; ++t) { c += r4[t]; cum4[t] = c; }
            float carry1 = warp_excl_from_total(c, lane);
            float c2 = 0.f, rec4[4];
            #pragma unroll
            for (int t = 0; t < 4; ++t) { c2 += ds4[t] * (cum4[t] + carry1); rec4[t] = c2; }
            float carry2 = warp_excl_from_total(c2, lane);
            float c3 = 0.f, cdf4[4], wb4[4];
            float wprev = (base == 0) ? 0.f : fmaxf(carry2, 0.f);
            #pragma unroll
            for (int t = 0; t < 4; ++t) {
                float wbk1 = fmaxf(rec4[t] + carry2, 0.f);
                wb4[t] = wbk1;
                c3 += 0.5f * (wbk1 + wprev) * ds4[t];
                cdf4[t] = c3;
                wprev = wbk1;
            }
            float carry3 = warp_excl_from_total(c3, lane);
            #pragma unroll
            for (int t = 0; t < 4; ++t) {
                int k = base + t;
                if (k < NB - 1) {
                    S.wb[k + 1]  = wb4[t];
                    S.cdf[k + 1] = cdf4[t] + carry3;
                }
            }
            if (lane == 0) { S.wb[0] = 0.f; S.cdf[0] = 0.f; }
            __syncwarp();

            // -- first-equal table: ieq[k] = lower_bound(cdf, cdf[k]) --
            {
                int run = -1, loc[4];
                #pragma unroll
                for (int t = 0; t < 4; ++t) {
                    int k = base + t;
                    int gk = -1;
                    if (k == 0) gk = 0;
                    else if (k < NB) gk = (S.cdf[k] != S.cdf[k - 1]) ? k : -1;
                    run = max(run, gk);
                    loc[t] = run;
                }
                int inc = run;
                #pragma unroll
                for (int o = 1; o < 32; o <<= 1) {
                    int y = __shfl_up_sync(0xffffffffu, inc, o);
                    if (lane >= o) inc = max(inc, y);
                }
                int excl = __shfl_up_sync(0xffffffffu, inc, 1);
                if (lane == 0) excl = -1;
                #pragma unroll
                for (int t = 0; t < 4; ++t) {
                    int k = base + t;
                    if (k < NB) S.ieq[k] = max(loc[t], excl);
                }
            }
            __syncwarp();

            acc += interp_level(S, psd, pwt, row, XP, (XP + 127) / 128, lane, scale);
        }
    }

    float wa = warpsum(acc);
    float P1 = warpsum(p1);
    float P2 = warpsum(p2);
    if (lane == 0)
        bacc[warp] = (row < R) ? (wa + (fabsf(P1) + fabsf(P2 * (1.f / 3.f))) * (0.01f / (float)R))
                               : 0.f;
    __syncthreads();
    if (threadIdx.x == 0) {
        float t = 0.f;
        #pragma unroll
        for (int i = 0; i < RPB; ++i) t += bacc[i];
        atomicAdd(out, t);
    }
}

__global__ __launch_bounds__(256)
void zero_kernel(float* out)
{
    int i = blockIdx.x * blockDim.x + threadIdx.x;   // one float4/int4 pair each
    if (i < (2 * NSEG) / 4) {
        ((float4*)g_seg)[i] = make_float4(0.f, 0.f, 0.f, 0.f);
        ((int4*)g_cnt)[i]   = make_int4(0, 0, 0, 0);
    }
    if (i == 0) out[0] = 0.f;
}

__global__ __launch_bounds__(256)
void hash_reduce(float* out)
{
    float v = 0.f;
    const int nvec = (2 * NSEG) / 4;
    for (int i = blockIdx.x * blockDim.x + threadIdx.x; i < nvec;
         i += gridDim.x * blockDim.x) {
        float4 s = ((const float4*)g_seg)[i];
        int4   c = ((const int4*)g_cnt)[i];
        if (c.x > 0) v += s.x / (float)c.x;
        if (c.y > 0) v += s.y / (float)c.y;
        if (c.z > 0) v += s.z / (float)c.z;
        if (c.w > 0) v += s.w / (float)c.w;
    }
    v = warpsum(v);
    __shared__ float sh[8];
    int w = threadIdx.x >> 5, l = threadIdx.x & 31;
    if (l == 0) sh[w] = v;
    __syncthreads();
    if (w == 0) {
        float t = (l < 8) ? sh[l] : 0.f;
        t = warpsum(t);
        if (l == 0) atomicAdd(out, t * (0.1f / (2.f * (float)NSEG)));
    }
}

extern "C" void kernel_launch(void* const* d_in, const int* in_sizes, int n_in,
                              void* d_out, int out_size)
{
    const float* pd   = (const float*)d_in[0];
    const float* gt   = (const float*)d_in[1];
    const float* rsd  = (const float*)d_in[2];
    const float* rw   = (const float*)d_in[3];
    const float* psd0 = (const float*)d_in[4];
    const float* pwt0 = (const float*)d_in[5];
    const float* psd1 = (const float*)d_in[6];
    const float* pwt1 = (const float*)d_in[7];
    const float* emb0 = (const float*)d_in[8];
    const float* emb1 = (const float*)d_in[9];
    const int*   idx0 = (const int*)d_in[10];
    const int*   idx1 = (const int*)d_in[11];
    float* out = (float*)d_out;

    const int R   = in_sizes[0] / 3;
    const int XP0 = in_sizes[4] / R;
    const int XP1 = in_sizes[6] / R;
    const int M   = in_sizes[8] / 2;

    const int ROWB = (R + RPB - 1) / RPB;           // 512
    const int HB   = (M + 1023) / 1024;             // 192

    zero_kernel<<<((2 * NSEG) / 4 + 255) / 256, 256>>>(out);
    mega_kernel<<<ROWB + 2 * HB, 256>>>(pd, gt, rsd, rw,
                                        psd0, pwt0, psd1, pwt1,
                                        emb0, emb1, idx0, idx1,
                                        out, R, XP0, XP1, M, ROWB, HB);
    hash_reduce<<<64, 256>>>(out);
}

// round 4
// speedup vs baseline: 1.7859x; 1.2613x over previous
#include <cuda_runtime.h>

static constexpr int NV   = 48;
static constexpr int NP1  = 49;
static constexpr int NB   = 98;
static constexpr int NSEG = 65536;
static constexpr int RPB  = 8;     // rows per block (8 warps)
static constexpr int HE   = 8;     // hash windows per warp (32*HE = 256 elems/warp)

static constexpr float PW0 = 0.01f;
static constexpr float PW1 = 0.005f;

// self-cleaning accumulator (zero-initialized once; every launch restores 0/0)
__device__ float    g_accum = 0.f;
__device__ unsigned g_ctr   = 0u;

struct RowS {
    float sd[NP1];
    float w[NV];
    float wn[NV];
    float bounds[NB];
    float rs[NB];      // also temp for midpoints
    float wb[NB];
    float cdf[NB];
    int   ieq[NB];     // first index of equal-cdf run
    float res[260];
};

__device__ __forceinline__ float warpsum(float v) {
    #pragma unroll
    for (int o = 16; o; o >>= 1) v += __shfl_xor_sync(0xffffffffu, v, o);
    return v;
}

__device__ __forceinline__ float warp_excl_from_total(float tot, int lane) {
    float inc = tot;
    #pragma unroll
    for (int o = 1; o < 32; o <<= 1) {
        float y = __shfl_up_sync(0xffffffffu, inc, o);
        if (lane >= o) inc += y;
    }
    return inc - tot;
}

// interp over XP points in strips of 128 (4 per lane, stride-32 layout)
__device__ __forceinline__ float interp_level(RowS& S, const float* __restrict__ psd,
                                              const float* __restrict__ pwt,
                                              int row, int XP, int nstrip,
                                              int lane, float scale)
{
    const float cdfN = S.cdf[NB - 1];
    int kprev = 0;
    #pragma unroll 1
    for (int s = 0; s < nstrip; ++s) {
        float x[4]; int lo[4], hi[4]; bool act[4];
        #pragma unroll
        for (int j = 0; j < 4; ++j) {
            int t = s * 128 + j * 32 + lane;
            act[j] = t < XP;
            x[j] = act[j] ? psd[row * XP + t] : 0.f;
            lo[j] = kprev; hi[j] = NB;
        }
        #pragma unroll
        for (int st = 0; st < 7; ++st) {
            #pragma unroll
            for (int j = 0; j < 4; ++j) {
                if (act[j] && lo[j] < hi[j]) {
                    int mid = (lo[j] + hi[j]) >> 1;
                    if (S.bounds[mid] <= x[j]) lo[j] = mid + 1; else hi[j] = mid;
                }
            }
        }
        #pragma unroll
        for (int j = 0; j < 4; ++j) {
            if (!act[j]) continue;
            int k  = lo[j] - 1;
            int kk = k < 0 ? 0 : k;
            kprev  = kk;
            float fcdf0 = S.cdf[kk];
            int   i0    = S.ieq[kk];
            float xp0   = S.bounds[kk];
            int i1; float xp1;
            if (k < 0)            { i1 = 0; xp1 = S.bounds[0]; }
            else if (k >= NB - 1) { i1 = 0; xp1 = S.bounds[NB - 1]; }
            else {
                float ck1 = S.cdf[k + 1];
                i1 = (ck1 == cdfN) ? 0 : (k + 1);
                xp1 = S.bounds[k + 1];
            }
            float fp0 = S.wb[i0], fp1 = S.wb[i1];
            float num = x[j] - xp0, den = xp1 - xp0;
            float off = (den > 0.f) ? fminf(fmaxf(num / den, 0.f), 1.f)
                                    : (num > 0.f ? 1.f : 0.f);
            S.res[s * 128 + j * 32 + lane] =
                fcdf0 + num * (fp0 + fp1 * off + fp0 * (1.f - off)) * 0.5f;
        }
    }
    __syncwarp();

    float lsum = 0.f;
    for (int t = lane; t < XP - 1; t += 32) {
        float ws  = S.res[t + 1] - S.res[t];
        float pwv = pwt[row * (XP - 1) + t];
        float d = ws - pwv;
        if (d > 0.f) lsum += d * d / (pwv + 1e-5f);
    }
    __syncwarp();
    return lsum * scale;
}

__global__ __launch_bounds__(256)
void mega_kernel(const float* __restrict__ pd, const float* __restrict__ gt,
                 const float* __restrict__ rsd, const float* __restrict__ rw,
                 const float* __restrict__ psd0, const float* __restrict__ pwt0,
                 const float* __restrict__ psd1, const float* __restrict__ pwt1,
                 const float* __restrict__ emb0, const float* __restrict__ emb1,
                 const int* __restrict__ idx0, const int* __restrict__ idx1,
                 float* __restrict__ out, int R, int XP0, int XP1, int M,
                 int ROWB, int HBL)
{
    __shared__ RowS sm[RPB];
    __shared__ float bacc[RPB];

    const int warp = threadIdx.x >> 5;
    const int lane = threadIdx.x & 31;

    if (blockIdx.x >= (unsigned)ROWB) {
        // ================= hash role: run-ownership, no scratch =================
        int h     = blockIdx.x - ROWB;
        int level = h / HBL;
        int bh    = h % HBL;
        const float* emb = level ? emb1 : emb0;
        const int*   idx = level ? idx1 : idx0;
        const float hscale = 0.1f / (2.f * (float)NSEG);

        float acc = 0.f;
        const int warpbase = (bh * RPB + warp) * (32 * HE);
        #pragma unroll 1
        for (int e = 0; e < HE; ++e) {
            int b = warpbase + e * 32;
            if (b >= M) break;
            int i = b + lane;
            bool ok = i < M;
            int s = ok ? idx[i] : -1;
            float v = 0.f;
            if (ok) {
                float2 e2 = ((const float2*)emb)[i];
                v = e2.x * e2.x + e2.y * e2.y;
            }
            int prev = -2;
            if (lane == 0 && b > 0) prev = idx[b - 1];
            prev = __shfl_sync(0xffffffffu, prev, 0);

            unsigned m = __match_any_sync(0xffffffffu, s);
            int leader = __ffs(m) - 1;
            int hib = 31 - __clz(m);
            #pragma unroll
            for (int o = 16; o; o >>= 1) {
                float y = __shfl_down_sync(0xffffffffu, v, o);
                if (lane + o <= hib) v += y;
            }
            if (ok && lane == leader && !(leader == 0 && s == prev)) {
                int cnt = __popc(m);
                if (hib == 31) {                  // run may extend past window
                    int j = b + 32;
                    while (j < M && idx[j] == s) {
                        float2 e2 = ((const float2*)emb)[j];
                        v += e2.x * e2.x + e2.y * e2.y;
                        ++cnt; ++j;
                    }
                }
                acc += v / (float)cnt;
            }
        }
        float wsum = warpsum(acc * hscale);
        if (lane == 0) bacc[warp] = wsum;
    } else {
        // ================= row role =================
        const int row = blockIdx.x * RPB + warp;
        float acc = 0.f;
        float p1 = 0.f, p2 = 0.f;

        if (row < R) {
            RowS& S = sm[warp];

            for (int i = lane; i < NP1; i += 32) S.sd[i] = rsd[row * NP1 + i];
            __syncwarp();
            for (int i = lane; i < NV; i += 32) {
                float wv = rw[row * NV + i];
                S.w[i]  = wv;
                S.wn[i] = wv / (S.sd[i + 1] - S.sd[i] + 1e-8f);
                S.rs[i] = 0.5f * (S.sd[i + 1] + S.sd[i]);   // midpoints (temp)
            }
            __syncwarp();

            if (lane < 3) {
                float d = pd[row * 3 + lane] - gt[row * 3 + lane];
                acc += d * d / (3.f * (float)R);
            }

            for (int n = lane; n < NV; n += 32) {
                float mn = S.rs[n];
                float wv = S.w[n];
                float inner = 0.f;
                #pragma unroll 8
                for (int m = 0; m < NV; ++m)
                    inner += S.w[m] * fabsf(mn - S.rs[m]);
                p1 += wv * inner;
                p2 += wv * wv * (S.sd[n + 1] - S.sd[n]);
            }
            __syncwarp();

            #pragma unroll 1
            for (int lev = 0; lev < 2; ++lev) {
                const float pw = lev ? PW1 : PW0;
                const float* psd = lev ? psd1 : psd0;
                const float* pwt = lev ? pwt1 : pwt0;
                const int XP = lev ? XP1 : XP0;
                const float scale = 1.f / ((float)R * (float)(XP - 1));

                // batched stable merge (rank-scatter), 4 per lane
                {
                    int   mlo[4]; float mval[4]; int mj[4]; bool mok[4], mlow[4];
                    #pragma unroll
                    for (int q = 0; q < 4; ++q) {
                        int p = lane + 32 * q;
                        mok[q]  = p < NB;
                        mlow[q] = p < NP1;
                        int j   = mlow[q] ? p : p - NP1;
                        mj[q]   = j;
                        mval[q] = mok[q] ? (mlow[q] ? S.sd[j] - pw : S.sd[j] + pw) : 0.f;
                        mlo[q]  = 0;
                    }
                    int mhi[4] = {NP1, NP1, NP1, NP1};
                    #pragma unroll
                    for (int s = 0; s < 6; ++s) {
                        #pragma unroll
                        for (int q = 0; q < 4; ++q) {
                            if (mok[q] && mlo[q] < mhi[q]) {
                                int mid = (mlo[q] + mhi[q]) >> 1;
                                float sv = S.sd[mid];
                                bool adv = mlow[q] ? (sv + pw < mval[q]) : (sv - pw <= mval[q]);
                                if (adv) mlo[q] = mid + 1; else mhi[q] = mid;
                            }
                        }
                    }
                    #pragma unroll
                    for (int q = 0; q < 4; ++q) {
                        if (mok[q]) {
                            int j = mj[q];
                            float d0 = (j < NV ? S.wn[j] : 0.f) - (j > 0 ? S.wn[j - 1] : 0.f);
                            float rv = (mlow[q] ? d0 : -d0) / (2.f * pw);
                            int pos = j + mlo[q];
                            S.bounds[pos] = mval[q];
                            S.rs[pos] = rv;
                        }
                    }
                }
                __syncwarp();

                // three blocked scans over 97 elements
                const int base = lane * 4;
                float r4[4], ds4[4];
                #pragma unroll
                for (int t = 0; t < 4; ++t) {
                    int k = base + t;
                    bool v = (k < NB - 1);
                    r4[t]  = v ? S.rs[k] : 0.f;
                    ds4[t] = v ? (S.bounds[k + 1] - S.bounds[k]) : 0.f;
                }
                float c = 0.f, cum4[4];
                #pragma unroll
                for (int t = 0; t < 4; ++t) { c += r4[t]; cum4[t] = c; }
                float carry1 = warp_excl_from_total(c, lane);
                float c2 = 0.f, rec4[4];
                #pragma unroll
                for (int t = 0; t < 4; ++t) { c2 += ds4[t] * (cum4[t] + carry1); rec4[t] = c2; }
                float carry2 = warp_excl_from_total(c2, lane);
                float c3 = 0.f, cdf4[4], wb4[4];
                float wprev = (base == 0) ? 0.f : fmaxf(carry2, 0.f);
                #pragma unroll
                for (int t = 0; t < 4; ++t) {
                    float wbk1 = fmaxf(rec4[t] + carry2, 0.f);
                    wb4[t] = wbk1;
                    c3 += 0.5f * (wbk1 + wprev) * ds4[t];
                    cdf4[t] = c3;
                    wprev = wbk1;
                }
                float carry3 = warp_excl_from_total(c3, lane);
                #pragma unroll
                for (int t = 0; t < 4; ++t) {
                    int k = base + t;
                    if (k < NB - 1) {
                        S.wb[k + 1]  = wb4[t];
                        S.cdf[k + 1] = cdf4[t] + carry3;
                    }
                }
                if (lane == 0) { S.wb[0] = 0.f; S.cdf[0] = 0.f; }
                __syncwarp();

                // first-equal table: ieq[k] = lower_bound(cdf, cdf[k])
                {
                    int run = -1, loc[4];
                    #pragma unroll
                    for (int t = 0; t < 4; ++t) {
                        int k = base + t;
                        int gk = -1;
                        if (k == 0) gk = 0;
                        else if (k < NB) gk = (S.cdf[k] != S.cdf[k - 1]) ? k : -1;
                        run = max(run, gk);
                        loc[t] = run;
                    }
                    int inc = run;
                    #pragma unroll
                    for (int o = 1; o < 32; o <<= 1) {
                        int y = __shfl_up_sync(0xffffffffu, inc, o);
                        if (lane >= o) inc = max(inc, y);
                    }
                    int excl = __shfl_up_sync(0xffffffffu, inc, 1);
                    if (lane == 0) excl = -1;
                    #pragma unroll
                    for (int t = 0; t < 4; ++t) {
                        int k = base + t;
                        if (k < NB) S.ieq[k] = max(loc[t], excl);
                    }
                }
                __syncwarp();

                acc += interp_level(S, psd, pwt, row, XP, (XP + 127) / 128, lane, scale);
            }
        }

        float wa = warpsum(acc);
        float P1 = warpsum(p1);
        float P2 = warpsum(p2);
        if (lane == 0)
            bacc[warp] = (row < R)
                ? (wa + (fabsf(P1) + fabsf(P2 * (1.f / 3.f))) * (0.01f / (float)R))
                : 0.f;
    }

    // ================= common tail: block sum -> global accum -> last block writes =================
    __syncthreads();
    if (threadIdx.x == 0) {
        float t = 0.f;
        #pragma unroll
        for (int i = 0; i < RPB; ++i) t += bacc[i];
        atomicAdd(&g_accum, t);
        __threadfence();
        unsigned old = atomicAdd(&g_ctr, 1u);
        if (old == gridDim.x - 1) {
            float r = atomicExch(&g_accum, 0.f);   // read + reset for next launch
            out[0] = r;
            atomicExch(&g_ctr, 0u);
        }
    }
}

extern "C" void kernel_launch(void* const* d_in, const int* in_sizes, int n_in,
                              void* d_out, int out_size)
{
    const float* pd   = (const float*)d_in[0];
    const float* gt   = (const float*)d_in[1];
    const float* rsd  = (const float*)d_in[2];
    const float* rw   = (const float*)d_in[3];
    const float* psd0 = (const float*)d_in[4];
    const float* pwt0 = (const float*)d_in[5];
    const float* psd1 = (const float*)d_in[6];
    const float* pwt1 = (const float*)d_in[7];
    const float* emb0 = (const float*)d_in[8];
    const float* emb1 = (const float*)d_in[9];
    const int*   idx0 = (const int*)d_in[10];
    const int*   idx1 = (const int*)d_in[11];
    float* out = (float*)d_out;

    const int R   = in_sizes[0] / 3;
    const int XP0 = in_sizes[4] / R;
    const int XP1 = in_sizes[6] / R;
    const int M   = in_sizes[8] / 2;

    const int ROWB = (R + RPB - 1) / RPB;                        // 512
    const int HBL  = (M + RPB * 32 * HE - 1) / (RPB * 32 * HE);  // 96 per level

    mega_kernel<<<ROWB + 2 * HBL, 256>>>(pd, gt, rsd, rw,
                                         psd0, pwt0, psd1, pwt1,
                                         emb0, emb1, idx0, idx1,
                                         out, R, XP0, XP1, M, ROWB, HBL);
}

// round 5
// speedup vs baseline: 2.0579x; 1.1523x over previous
#include <cuda_runtime.h>

static constexpr int NV   = 48;
static constexpr int NP1  = 49;
static constexpr int NB   = 98;
static constexpr int NSEG = 65536;
static constexpr int RPB  = 8;     // rows per block (8 warps)
static constexpr int HE   = 8;     // hash windows per warp

static constexpr float PW0 = 0.01f;
static constexpr float PW1 = 0.005f;

// self-cleaning accumulator (zero-initialized; every launch restores 0/0)
__device__ float    g_accum = 0.f;
__device__ unsigned g_ctr   = 0u;

struct RowS {
    float sd[NP1];
    float w[NV];
    float wn[NV];
    float bounds[NB];
    float rs[NB];      // temp midpoints, then radio_sorted
    float wb[NB];
    float cdf[NB];
    int   ieq[NB];     // first index of equal-cdf run
};

__device__ __forceinline__ float warpsum(float v) {
    #pragma unroll
    for (int o = 16; o; o >>= 1) v += __shfl_xor_sync(0xffffffffu, v, o);
    return v;
}

__device__ __forceinline__ float warp_excl_from_total(float tot, int lane) {
    float inc = tot;
    #pragma unroll
    for (int o = 1; o < 32; o <<= 1) {
        float y = __shfl_up_sync(0xffffffffu, inc, o);
        if (lane >= o) inc += y;
    }
    return inc - tot;
}

// interp: lane owns contiguous chunk of CH diffs; 1 binary search + linear advance
template <int CH>
__device__ __forceinline__ float interp_chunk(RowS& S, const float* __restrict__ psd,
                                              const float* __restrict__ pwt,
                                              int row, int XP, int lane, float scale)
{
    const float cdfN = S.cdf[NB - 1];
    const int c0 = lane * CH;            // evals c0..c0+CH, diffs c0..c0+CH-1
    const float* px = psd + row * XP + c0;
    const float* pv = pwt + row * (XP - 1) + c0;

    float x0 = px[0];
    int lo = 0, hi = NB;
    #pragma unroll
    for (int st = 0; st < 7; ++st) {
        if (lo < hi) {
            int mid = (lo + hi) >> 1;
            if (S.bounds[mid] <= x0) lo = mid + 1; else hi = mid;
        }
    }
    int k = lo - 1;

    float lsum = 0.f, resprev = 0.f;
    #pragma unroll
    for (int j = 0; j <= CH; ++j) {
        float x = px[j];
        if (j > 0) {
            while (k + 1 < NB && S.bounds[k + 1] <= x) ++k;
        }
        int kk = k < 0 ? 0 : k;
        float fcdf0 = S.cdf[kk];
        int   i0    = S.ieq[kk];
        float xp0   = S.bounds[kk];
        int i1; float xp1;
        if (k < 0)            { i1 = 0; xp1 = S.bounds[0]; }
        else if (k >= NB - 1) { i1 = 0; xp1 = S.bounds[NB - 1]; }
        else {
            i1 = (S.cdf[k + 1] == cdfN) ? 0 : (k + 1);
            xp1 = S.bounds[k + 1];
        }
        float fp0 = S.wb[i0], fp1 = S.wb[i1];
        float num = x - xp0, den = xp1 - xp0;
        float off = (den > 0.f) ? fminf(fmaxf(num / den, 0.f), 1.f)
                                : (num > 0.f ? 1.f : 0.f);
        float res = fcdf0 + num * (fp0 + fp1 * off + fp0 * (1.f - off)) * 0.5f;
        if (j > 0) {
            float ws  = res - resprev;
            float pwv = pv[j - 1];
            float d = ws - pwv;
            if (d > 0.f) lsum += d * d / (pwv + 1e-5f);
        }
        resprev = res;
    }
    return lsum * scale;
}

__global__ __launch_bounds__(256)
void mega_kernel(const float* __restrict__ pd, const float* __restrict__ gt,
                 const float* __restrict__ rsd, const float* __restrict__ rw,
                 const float* __restrict__ psd0, const float* __restrict__ pwt0,
                 const float* __restrict__ psd1, const float* __restrict__ pwt1,
                 const float* __restrict__ emb0, const float* __restrict__ emb1,
                 const int* __restrict__ idx0, const int* __restrict__ idx1,
                 float* __restrict__ out, int R, int XP0, int XP1, int M,
                 int ROWB, int HBL)
{
    __shared__ RowS sm[RPB];
    __shared__ float bacc[RPB];

    const int warp = threadIdx.x >> 5;
    const int lane = threadIdx.x & 31;

    if (blockIdx.x >= (unsigned)ROWB) {
        // ================= hash role: run-ownership, no scratch =================
        int h     = blockIdx.x - ROWB;
        int level = h / HBL;
        int bh    = h % HBL;
        const float* emb = level ? emb1 : emb0;
        const int*   idx = level ? idx1 : idx0;
        const float hscale = 0.1f / (2.f * (float)NSEG);

        float acc = 0.f;
        const int warpbase = (bh * RPB + warp) * (32 * HE);
        #pragma unroll 1
        for (int e = 0; e < HE; ++e) {
            int b = warpbase + e * 32;
            if (b >= M) break;
            int i = b + lane;
            bool ok = i < M;
            int s = ok ? idx[i] : -1;
            float v = 0.f;
            if (ok) {
                float2 e2 = ((const float2*)emb)[i];
                v = e2.x * e2.x + e2.y * e2.y;
            }
            int prev = -2;
            if (lane == 0 && b > 0) prev = idx[b - 1];
            prev = __shfl_sync(0xffffffffu, prev, 0);

            unsigned m = __match_any_sync(0xffffffffu, s);
            int leader = __ffs(m) - 1;
            int hib = 31 - __clz(m);
            #pragma unroll
            for (int o = 16; o; o >>= 1) {
                float y = __shfl_down_sync(0xffffffffu, v, o);
                if (lane + o <= hib) v += y;
            }
            if (ok && lane == leader && !(leader == 0 && s == prev)) {
                int cnt = __popc(m);
                if (hib == 31) {                  // run extends past window
                    int j = b + 32;
                    while (j < M && idx[j] == s) {
                        float2 e2 = ((const float2*)emb)[j];
                        v += e2.x * e2.x + e2.y * e2.y;
                        ++cnt; ++j;
                    }
                }
                acc += v / (float)cnt;
            }
        }
        float wsum = warpsum(acc * hscale);
        if (lane == 0) bacc[warp] = wsum;
    } else {
        // ================= row role =================
        const int row = blockIdx.x * RPB + warp;
        float acc = 0.f;
        float p1 = 0.f, p2 = 0.f;

        if (row < R) {
            RowS& S = sm[warp];

            for (int i = lane; i < NP1; i += 32) S.sd[i] = rsd[row * NP1 + i];
            __syncwarp();
            for (int i = lane; i < NV; i += 32) {
                float wv = rw[row * NV + i];
                S.w[i]  = wv;
                S.wn[i] = wv / (S.sd[i + 1] - S.sd[i] + 1e-8f);
                S.rs[i] = 0.5f * (S.sd[i + 1] + S.sd[i]);   // midpoints (temp)
            }
            __syncwarp();

            if (lane < 3) {
                float d = pd[row * 3 + lane] - gt[row * 3 + lane];
                acc += d * d / (3.f * (float)R);
            }

            // ---- distortion via prefix sums (mid sorted ascending) ----
            {
                float w0 = 0.f, w1 = 0.f, m0 = 0.f, m1 = 0.f, d0 = 0.f, d1 = 0.f;
                if (lane < 24) {
                    int n0 = 2 * lane;
                    w0 = S.w[n0];     w1 = S.w[n0 + 1];
                    m0 = S.rs[n0];    m1 = S.rs[n0 + 1];
                    d0 = S.sd[n0 + 1] - S.sd[n0];
                    d1 = S.sd[n0 + 2] - S.sd[n0 + 1];
                }
                float sw  = w0 + w1;
                float swm = w0 * m0 + w1 * m1;
                float cA = warp_excl_from_total(sw, lane);
                float cB = warp_excl_from_total(swm, lane);
                p1 = 2.f * (w0 * (m0 * cA - cB)
                          + w1 * (m1 * (cA + w0) - (cB + w0 * m0)));
                p2 = w0 * w0 * d0 + w1 * w1 * d1;
            }

            #pragma unroll 1
            for (int lev = 0; lev < 2; ++lev) {
                const float pw = lev ? PW1 : PW0;
                const float* psd = lev ? psd1 : psd0;
                const float* pwt = lev ? pwt1 : pwt0;
                const int XP = lev ? XP1 : XP0;
                const float scale = 1.f / ((float)R * (float)(XP - 1));

                // batched stable merge (rank-scatter), 4 per lane
                {
                    int   mlo[4]; float mval[4]; int mj[4]; bool mok[4], mlow[4];
                    #pragma unroll
                    for (int q = 0; q < 4; ++q) {
                        int p = lane + 32 * q;
                        mok[q]  = p < NB;
                        mlow[q] = p < NP1;
                        int j   = mlow[q] ? p : p - NP1;
                        mj[q]   = j;
                        mval[q] = mok[q] ? (mlow[q] ? S.sd[j] - pw : S.sd[j] + pw) : 0.f;
                        mlo[q]  = 0;
                    }
                    int mhi[4] = {NP1, NP1, NP1, NP1};
                    #pragma unroll
                    for (int s = 0; s < 6; ++s) {
                        #pragma unroll
                        for (int q = 0; q < 4; ++q) {
                            if (mok[q] && mlo[q] < mhi[q]) {
                                int mid = (mlo[q] + mhi[q]) >> 1;
                                float sv = S.sd[mid];
                                bool adv = mlow[q] ? (sv + pw < mval[q]) : (sv - pw <= mval[q]);
                                if (adv) mlo[q] = mid + 1; else mhi[q] = mid;
                            }
                        }
                    }
                    #pragma unroll
                    for (int q = 0; q < 4; ++q) {
                        if (mok[q]) {
                            int j = mj[q];
                            float dd = (j < NV ? S.wn[j] : 0.f) - (j > 0 ? S.wn[j - 1] : 0.f);
                            float rv = (mlow[q] ? dd : -dd) / (2.f * pw);
                            int pos = j + mlo[q];
                            S.bounds[pos] = mval[q];
                            S.rs[pos] = rv;
                        }
                    }
                }
                __syncwarp();

                // three blocked scans over 97 elements
                const int base = lane * 4;
                float r4[4], ds4[4];
                #pragma unroll
                for (int t = 0; t < 4; ++t) {
                    int k = base + t;
                    bool v = (k < NB - 1);
                    r4[t]  = v ? S.rs[k] : 0.f;
                    ds4[t] = v ? (S.bounds[k + 1] - S.bounds[k]) : 0.f;
                }
                float c = 0.f, cum4[4];
                #pragma unroll
                for (int t = 0; t < 4; ++t) { c += r4[t]; cum4[t] = c; }
                float carry1 = warp_excl_from_total(c, lane);
                float c2 = 0.f, rec4[4];
                #pragma unroll
                for (int t = 0; t < 4; ++t) { c2 += ds4[t] * (cum4[t] + carry1); rec4[t] = c2; }
                float carry2 = warp_excl_from_total(c2, lane);
                float c3 = 0.f, cdf4[4], wb4[4];
                float wprev = (base == 0) ? 0.f : fmaxf(carry2, 0.f);
                #pragma unroll
                for (int t = 0; t < 4; ++t) {
                    float wbk1 = fmaxf(rec4[t] + carry2, 0.f);
                    wb4[t] = wbk1;
                    c3 += 0.5f * (wbk1 + wprev) * ds4[t];
                    cdf4[t] = c3;
                    wprev = wbk1;
                }
                float carry3 = warp_excl_from_total(c3, lane);
                #pragma unroll
                for (int t = 0; t < 4; ++t) {
                    int k = base + t;
                    if (k < NB - 1) {
                        S.wb[k + 1]  = wb4[t];
                        S.cdf[k + 1] = cdf4[t] + carry3;
                    }
                }
                if (lane == 0) { S.wb[0] = 0.f; S.cdf[0] = 0.f; }
                __syncwarp();

                // first-equal table: ieq[k] = lower_bound(cdf, cdf[k])
                {
                    int run = -1, loc[4];
                    #pragma unroll
                    for (int t = 0; t < 4; ++t) {
                        int k = base + t;
                        int gk = -1;
                        if (k == 0) gk = 0;
                        else if (k < NB) gk = (S.cdf[k] != S.cdf[k - 1]) ? k : -1;
                        run = max(run, gk);
                        loc[t] = run;
                    }
                    int inc = run;
                    #pragma unroll
                    for (int o = 1; o < 32; o <<= 1) {
                        int y = __shfl_up_sync(0xffffffffu, inc, o);
                        if (lane >= o) inc = max(inc, y);
                    }
                    int excl = __shfl_up_sync(0xffffffffu, inc, 1);
                    if (lane == 0) excl = -1;
                    #pragma unroll
                    for (int t = 0; t < 4; ++t) {
                        int k = base + t;
                        if (k < NB) S.ieq[k] = max(loc[t], excl);
                    }
                }
                __syncwarp();

                if (lev == 0) acc += interp_chunk<8>(S, psd, pwt, row, XP, lane, scale);
                else          acc += interp_chunk<3>(S, psd, pwt, row, XP, lane, scale);
                __syncwarp();
            }
        }

        float wa = warpsum(acc);
        float P1 = warpsum(p1);
        float P2 = warpsum(p2);
        if (lane == 0)
            bacc[warp] = (row < R)
                ? (wa + (fabsf(P1) + fabsf(P2 * (1.f / 3.f))) * (0.01f / (float)R))
                : 0.f;
    }

    // ===== tail: block sum -> global accum -> last block writes out =====
    __syncthreads();
    if (threadIdx.x == 0) {
        float t = 0.f;
        #pragma unroll
        for (int i = 0; i < RPB; ++i) t += bacc[i];
        atomicAdd(&g_accum, t);
        __threadfence();
        unsigned old = atomicAdd(&g_ctr, 1u);
        if (old == gridDim.x - 1) {
            float r = atomicExch(&g_accum, 0.f);
            out[0] = r;
            atomicExch(&g_ctr, 0u);
        }
    }
}

extern "C" void kernel_launch(void* const* d_in, const int* in_sizes, int n_in,
                              void* d_out, int out_size)
{
    const float* pd   = (const float*)d_in[0];
    const float* gt   = (const float*)d_in[1];
    const float* rsd  = (const float*)d_in[2];
    const float* rw   = (const float*)d_in[3];
    const float* psd0 = (const float*)d_in[4];
    const float* pwt0 = (const float*)d_in[5];
    const float* psd1 = (const float*)d_in[6];
    const float* pwt1 = (const float*)d_in[7];
    const float* emb0 = (const float*)d_in[8];
    const float* emb1 = (const float*)d_in[9];
    const int*   idx0 = (const int*)d_in[10];
    const int*   idx1 = (const int*)d_in[11];
    float* out = (float*)d_out;

    const int R   = in_sizes[0] / 3;
    const int XP0 = in_sizes[4] / R;
    const int XP1 = in_sizes[6] / R;
    const int M   = in_sizes[8] / 2;

    const int ROWB = (R + RPB - 1) / RPB;                        // 512
    const int HBL  = (M + RPB * 32 * HE - 1) / (RPB * 32 * HE);  // 96 per level

    mega_kernel<<<ROWB + 2 * HBL, 256>>>(pd, gt, rsd, rw,
                                         psd0, pwt0, psd1, pwt1,
                                         emb0, emb1, idx0, idx1,
                                         out, R, XP0, XP1, M, ROWB, HBL);
}